// round 1
// baseline (speedup 1.0000x reference)
#include <cuda_runtime.h>
#include <math.h>

#define ROWS 32768
#define COLS 1000
#define VEC  (COLS / 4)        // 250 float4 per row
#define WARPS_PER_BLOCK 8
#define BLOCKS (ROWS / WARPS_PER_BLOCK)   // 4096
#define THREADS (WARPS_PER_BLOCK * 32)    // 256

// Per-block partial sums (double). Fully rewritten every launch -> no zeroing
// kernel needed, deterministic across graph replays.
__device__ double g_partial[BLOCKS];

__global__ __launch_bounds__(THREADS)
void lsep_rows_kernel(const float4* __restrict__ in, const int4* __restrict__ tg) {
    const int w    = threadIdx.x >> 5;
    const int lane = threadIdx.x & 31;
    const int row  = blockIdx.x * WARPS_PER_BLOCK + w;

    const float4* __restrict__ ip = in + (size_t)row * VEC;
    const int4*   __restrict__ tp = tg + (size_t)row * VEC;

    float sneg = 0.0f, spos = 0.0f;

    // Lane-strided float4 walk over the row: each warp iteration reads
    // 512B input + 512B target, fully coalesced.
    for (int j = lane; j < VEC; j += 32) {
        const float4 x = ip[j];
        const int4   t = tp[j];
        {
            float e = __expf(t.x ? -x.x : x.x);
            if (t.x) spos += e; else sneg += e;
        }
        {
            float e = __expf(t.y ? -x.y : x.y);
            if (t.y) spos += e; else sneg += e;
        }
        {
            float e = __expf(t.z ? -x.z : x.z);
            if (t.z) spos += e; else sneg += e;
        }
        {
            float e = __expf(t.w ? -x.w : x.w);
            if (t.w) spos += e; else sneg += e;
        }
    }

    // Warp reduction of both row sums.
    #pragma unroll
    for (int o = 16; o > 0; o >>= 1) {
        sneg += __shfl_down_sync(0xffffffffu, sneg, o);
        spos += __shfl_down_sync(0xffffffffu, spos, o);
    }

    __shared__ double smem[WARPS_PER_BLOCK];
    if (lane == 0)
        smem[w] = (double)sneg * (double)spos;
    __syncthreads();

    if (threadIdx.x == 0) {
        double s = 0.0;
        #pragma unroll
        for (int i = 0; i < WARPS_PER_BLOCK; i++) s += smem[i];
        g_partial[blockIdx.x] = s;
    }
}

__global__ __launch_bounds__(512)
void lsep_final_kernel(float* __restrict__ out) {
    __shared__ double smem[512];
    double s = 0.0;
    for (int i = threadIdx.x; i < BLOCKS; i += 512)
        s += g_partial[i];
    smem[threadIdx.x] = s;
    __syncthreads();
    #pragma unroll
    for (int o = 256; o > 0; o >>= 1) {
        if (threadIdx.x < o) smem[threadIdx.x] += smem[threadIdx.x + o];
        __syncthreads();
    }
    if (threadIdx.x == 0)
        out[0] = (float)log1p(smem[0]);
}

extern "C" void kernel_launch(void* const* d_in, const int* in_sizes, int n_in,
                              void* d_out, int out_size) {
    const float4* in = (const float4*)d_in[0];
    const int4*   tg = (const int4*)d_in[1];
    float* out = (float*)d_out;

    lsep_rows_kernel<<<BLOCKS, THREADS>>>(in, tg);
    lsep_final_kernel<<<1, 512>>>(out);
}

// round 2
// speedup vs baseline: 1.0712x; 1.0712x over previous
#include <cuda_runtime.h>
#include <math.h>

#define ROWS 32768
#define COLS 1000
#define VEC  (COLS / 4)                   // 250 float4 per row
#define WARPS_PER_BLOCK 8
#define ROWS_PER_WARP 2
#define ROWS_PER_BLOCK (WARPS_PER_BLOCK * ROWS_PER_WARP)   // 16
#define BLOCKS (ROWS / ROWS_PER_BLOCK)    // 2048
#define THREADS (WARPS_PER_BLOCK * 32)    // 256

// Per-block partials; fully rewritten every launch (no zeroing needed).
__device__ double g_partial[BLOCKS];
// Ticket counter for last-block-done. Reset to 0 by the last block each
// launch -> deterministic across graph replays.
__device__ unsigned int g_ticket = 0;

__global__ __launch_bounds__(THREADS)
void lsep_fused_kernel(const float4* __restrict__ in,
                       const int4*  __restrict__ tg,
                       float* __restrict__ out) {
    const int w    = threadIdx.x >> 5;
    const int lane = threadIdx.x & 31;
    const int row0 = (blockIdx.x * WARPS_PER_BLOCK + w) * ROWS_PER_WARP;

    const float4* __restrict__ ip0 = in + (size_t)row0 * VEC;
    const int4*   __restrict__ tp0 = tg + (size_t)row0 * VEC;
    const float4* __restrict__ ip1 = ip0 + VEC;
    const int4*   __restrict__ tp1 = tp0 + VEC;

    float sneg0 = 0.0f, spos0 = 0.0f;
    float sneg1 = 0.0f, spos1 = 0.0f;

    // Two rows per warp: 4 independent 16B loads in flight per iteration.
    for (int j = lane; j < VEC; j += 32) {
        const float4 x0 = ip0[j];
        const int4   t0 = tp0[j];
        const float4 x1 = ip1[j];
        const int4   t1 = tp1[j];

        {
            float e = __expf(t0.x ? -x0.x : x0.x);
            if (t0.x) spos0 += e; else sneg0 += e;
        }
        {
            float e = __expf(t0.y ? -x0.y : x0.y);
            if (t0.y) spos0 += e; else sneg0 += e;
        }
        {
            float e = __expf(t0.z ? -x0.z : x0.z);
            if (t0.z) spos0 += e; else sneg0 += e;
        }
        {
            float e = __expf(t0.w ? -x0.w : x0.w);
            if (t0.w) spos0 += e; else sneg0 += e;
        }
        {
            float e = __expf(t1.x ? -x1.x : x1.x);
            if (t1.x) spos1 += e; else sneg1 += e;
        }
        {
            float e = __expf(t1.y ? -x1.y : x1.y);
            if (t1.y) spos1 += e; else sneg1 += e;
        }
        {
            float e = __expf(t1.z ? -x1.z : x1.z);
            if (t1.z) spos1 += e; else sneg1 += e;
        }
        {
            float e = __expf(t1.w ? -x1.w : x1.w);
            if (t1.w) spos1 += e; else sneg1 += e;
        }
    }

    // Warp reduction of all four row sums.
    #pragma unroll
    for (int o = 16; o > 0; o >>= 1) {
        sneg0 += __shfl_down_sync(0xffffffffu, sneg0, o);
        spos0 += __shfl_down_sync(0xffffffffu, spos0, o);
        sneg1 += __shfl_down_sync(0xffffffffu, sneg1, o);
        spos1 += __shfl_down_sync(0xffffffffu, spos1, o);
    }

    __shared__ double smem[WARPS_PER_BLOCK];
    __shared__ bool   s_last;
    if (lane == 0)
        smem[w] = (double)sneg0 * (double)spos0 + (double)sneg1 * (double)spos1;
    __syncthreads();

    if (threadIdx.x == 0) {
        double s = 0.0;
        #pragma unroll
        for (int i = 0; i < WARPS_PER_BLOCK; i++) s += smem[i];
        g_partial[blockIdx.x] = s;
        // Make the partial visible, then take a ticket.
        __threadfence();
        unsigned int t = atomicAdd(&g_ticket, 1u);
        s_last = (t == (unsigned int)(gridDim.x - 1));
    }
    __syncthreads();

    if (s_last) {
        // Last block: reduce all partials (L2-hot) and emit the loss.
        double s = 0.0;
        for (int i = threadIdx.x; i < BLOCKS; i += THREADS)
            s += g_partial[i];
        #pragma unroll
        for (int o = 16; o > 0; o >>= 1)
            s += __shfl_down_sync(0xffffffffu, s, o);

        __shared__ double smem2[WARPS_PER_BLOCK];
        if (lane == 0) smem2[w] = s;
        __syncthreads();
        if (threadIdx.x == 0) {
            double tot = 0.0;
            #pragma unroll
            for (int i = 0; i < WARPS_PER_BLOCK; i++) tot += smem2[i];
            out[0] = (float)log1p(tot);
            g_ticket = 0;   // reset for next graph replay
        }
    }
}

extern "C" void kernel_launch(void* const* d_in, const int* in_sizes, int n_in,
                              void* d_out, int out_size) {
    const float4* in = (const float4*)d_in[0];
    const int4*   tg = (const int4*)d_in[1];
    float* out = (float*)d_out;

    lsep_fused_kernel<<<BLOCKS, THREADS>>>(in, tg, out);
}